// round 6
// baseline (speedup 1.0000x reference)
#include <cuda_runtime.h>
#include <cuda_bf16.h>
#include <stdint.h>

// ---------------- problem constants ----------------
#define NBATCH 128
#define SEQ    2048
#define DIM    256          // K (features)
#define ADIM   128          // N (attention dim)
#define TILES  2048         // M-tiles of 128 rows
#define GRID   152
#define NTHR   512

// smem layout (bytes)
#define SM_WF     0                   // 131072: W fragments (uint4 per (j,nf,lane))
#define OFF_SE    131072              // float[2][128] exp(score), double buffered
#define OFF_SSC   (131072 + 1024)     // float[256] score partials (two n-halves)
#define OFF_SRED  (131072 + 2048)     // float[256] weighted-sum half combine
#define OFF_SBIAS (131072 + 3072)     // float[128]
#define OFF_SCV   (131072 + 3584)     // float[128]
#define SM_TOTAL  (131072 + 4096)

// ---------------- device scratch ----------------
__device__ float g_partial[TILES * DIM];          // 2 MB
__device__ float g_esum[TILES];
__device__ uint4 g_Wfrag[16 * 16 * 32];           // [kstep][nfrag][lane] = {hi0,hi1,lo0,lo1}

// ---------------- helpers ----------------
__device__ __forceinline__ uint32_t pkbf(float a, float b) {
    __nv_bfloat162 t = __floats2bfloat162_rn(a, b);
    return *(uint32_t*)&t;
}
__device__ __forceinline__ void split2(float a, float b, uint32_t& hi, uint32_t& lo) {
    float ra = __bfloat162float(__float2bfloat16(a));
    float rb = __bfloat162float(__float2bfloat16(b));
    hi = pkbf(a, b);
    lo = pkbf(a - ra, b - rb);
}
__device__ __forceinline__ void mma_bf16(float c[4], uint32_t a0, uint32_t a1,
                                         uint32_t a2, uint32_t a3,
                                         uint32_t b0, uint32_t b1) {
    asm volatile(
        "mma.sync.aligned.m16n8k16.row.col.f32.bf16.bf16.f32 "
        "{%0,%1,%2,%3}, {%4,%5,%6,%7}, {%8,%9}, {%0,%1,%2,%3};"
        : "+f"(c[0]), "+f"(c[1]), "+f"(c[2]), "+f"(c[3])
        : "r"(a0), "r"(a1), "r"(a2), "r"(a3), "r"(b0), "r"(b1));
}
__device__ __forceinline__ float fast_tanh(float v) {
    float e = __expf(2.0f * v);
    return 1.0f - __fdividef(2.0f, e + 1.0f);
}

// ---------------- W pre-conversion into fragment layout ----------------
__global__ void wprep(const float* __restrict__ w) {
    int idx = blockIdx.x * 256 + threadIdx.x;      // 8192 total
    if (idx >= 16 * 16 * 32) return;
    int lane = idx & 31, nf = (idx >> 5) & 15, j = idx >> 9;
    int g = lane >> 2, tig = lane & 3;
    int n = nf * 8 + g;
    int k0 = j * 16 + tig * 2;
    float w00 = w[(k0 + 0) * ADIM + n], w01 = w[(k0 + 1) * ADIM + n];
    float w80 = w[(k0 + 8) * ADIM + n], w81 = w[(k0 + 9) * ADIM + n];
    uint4 v;
    split2(w00, w01, v.x, v.z);
    split2(w80, w81, v.y, v.w);
    g_Wfrag[idx] = v;
}

// ---------------- main persistent kernel ----------------
__global__ void __launch_bounds__(NTHR, 1)
attn_mma(const float* __restrict__ x,
         const float* __restrict__ bias,
         const float* __restrict__ cvec)
{
    extern __shared__ char smem[];
    uint4* sWf   = (uint4*)(smem + SM_WF);
    float* sE0   = (float*)(smem + OFF_SE);          // [2][128]
    float* sSc   = (float*)(smem + OFF_SSC);         // [2][128] n-half partials
    float* sRed  = (float*)(smem + OFF_SRED);        // [256]
    float* sBias = (float*)(smem + OFF_SBIAS);
    float* sCv   = (float*)(smem + OFF_SCV);

    const int tid   = threadIdx.x;
    const int wid   = tid >> 5;
    const int lane  = tid & 31;
    const int g     = lane >> 2;      // 0..7
    const int tig   = lane & 3;       // 0..3
    const int mwarp = wid & 7;        // M-row group
    const int nhalf = wid >> 3;       // N half (0: cols 0-63, 1: cols 64-127)

    // weighted-sum assignment: feature d, t-half h
    const int d_ws = tid & 255;
    const int h_ws = tid >> 8;

    if (tid < 128) { sBias[tid] = bias[tid]; sCv[tid] = cvec[tid]; }
    {   // copy W fragments from L2 into smem
        #pragma unroll
        for (int i = 0; i < 16; i++) sWf[tid + i * NTHR] = g_Wfrag[tid + i * NTHR];
    }
    __syncthreads();

    int lastT = -1, lastbuf = 0;

    int it = 0;
    for (int T = blockIdx.x; T < TILES; T += gridDim.x, it++) {
        const int buf = it & 1;
        const size_t row0 = (size_t)T * 128;
        const float* xr1 = x + (row0 + (size_t)(mwarp * 16 + g)) * DIM + 2 * tig;
        const float* xr2 = xr1 + (size_t)8 * DIM;

        // interleaved weighted sum of previous tile
        const int Tprev = T - GRID;
        const bool havePrev = (it > 0);
        const float* xprev = x + ((size_t)(havePrev ? Tprev : T) * 128 + h_ws * 64) * DIM + d_ws;
        const float* sEp = sE0 + (buf ^ 1) * 128 + h_ws * 64;
        float wacc = 0.0f;

        float acc[8][4];
        #pragma unroll
        for (int nf = 0; nf < 8; nf++)
            #pragma unroll
            for (int c = 0; c < 4; c++) acc[nf][c] = 0.0f;

        float2 n0 = *(const float2*)(xr1);
        float2 n1 = *(const float2*)(xr2);
        float2 n2 = *(const float2*)(xr1 + 8);
        float2 n3 = *(const float2*)(xr2 + 8);

        #pragma unroll 1
        for (int j = 0; j < 16; j++) {
            // issue prev-tile weighted-sum loads early (hide under MMAs)
            float wv[4];
            if (havePrev) {
                #pragma unroll
                for (int q = 0; q < 4; q++)
                    wv[q] = __ldg(xprev + (size_t)(j * 4 + q) * DIM);
            }

            float2 c0 = n0, c1 = n1, c2 = n2, c3 = n3;
            if (j < 15) {
                int o = (j + 1) * 16;
                n0 = *(const float2*)(xr1 + o);
                n1 = *(const float2*)(xr2 + o);
                n2 = *(const float2*)(xr1 + o + 8);
                n3 = *(const float2*)(xr2 + o + 8);
            }
            uint32_t ah0, ah1, ah2, ah3, al0, al1, al2, al3;
            split2(c0.x, c0.y, ah0, al0);
            split2(c1.x, c1.y, ah1, al1);
            split2(c2.x, c2.y, ah2, al2);
            split2(c3.x, c3.y, ah3, al3);

            const uint4* bp = sWf + (j * 16 + nhalf * 8) * 32 + lane;
            #pragma unroll
            for (int nf = 0; nf < 8; nf++) {
                uint4 B = bp[nf * 32];
                mma_bf16(acc[nf], ah0, ah1, ah2, ah3, B.x, B.y);   // hi*hi
                mma_bf16(acc[nf], ah0, ah1, ah2, ah3, B.z, B.w);   // hi*lo
                mma_bf16(acc[nf], al0, al1, al2, al3, B.x, B.y);   // lo*hi
            }

            if (havePrev) {
                #pragma unroll
                for (int q = 0; q < 4; q++)
                    wacc = fmaf(sEp[j * 4 + q], wv[q], wacc);
            }
        }

        // stage weighted-sum half result
        if (havePrev) {
            if (h_ws == 0) sRed[d_ws] = wacc;
        }

        // ---- score partials over this warp's 64 columns ----
        {
            float p1 = 0.0f, p2 = 0.0f;
            #pragma unroll
            for (int nf = 0; nf < 8; nf++) {
                int col = nhalf * 64 + nf * 8 + 2 * tig;
                p1 += sCv[col]     * fast_tanh(acc[nf][0] + sBias[col]);
                p1 += sCv[col + 1] * fast_tanh(acc[nf][1] + sBias[col + 1]);
                p2 += sCv[col]     * fast_tanh(acc[nf][2] + sBias[col]);
                p2 += sCv[col + 1] * fast_tanh(acc[nf][3] + sBias[col + 1]);
            }
            p1 += __shfl_xor_sync(0xFFFFFFFFu, p1, 1);
            p1 += __shfl_xor_sync(0xFFFFFFFFu, p1, 2);
            p2 += __shfl_xor_sync(0xFFFFFFFFu, p2, 1);
            p2 += __shfl_xor_sync(0xFFFFFFFFu, p2, 2);
            if (tig == 0) {
                sSc[nhalf * 128 + mwarp * 16 + g]     = p1;
                sSc[nhalf * 128 + mwarp * 16 + g + 8] = p2;
            }
        }
        __syncthreads();   // sync #1: sRed h0 + score partials visible

        if (havePrev && h_ws == 1)
            g_partial[(size_t)Tprev * DIM + d_ws] = sRed[d_ws] + wacc;

        if (tid < 128) {
            float* sEc = sE0 + buf * 128;
            sEc[tid] = __expf(sSc[tid] + sSc[128 + tid]);
        }
        __syncthreads();   // sync #2: sE[buf] visible (esum + next tile reads)

        if (tid < 32) {
            const float* sEc = sE0 + buf * 128;
            float e = sEc[tid] + sEc[tid + 32] + sEc[tid + 64] + sEc[tid + 96];
            e += __shfl_xor_sync(0xFFFFFFFFu, e, 16);
            e += __shfl_xor_sync(0xFFFFFFFFu, e, 8);
            e += __shfl_xor_sync(0xFFFFFFFFu, e, 4);
            e += __shfl_xor_sync(0xFFFFFFFFu, e, 2);
            e += __shfl_xor_sync(0xFFFFFFFFu, e, 1);
            if (tid == 0) g_esum[T] = e;
        }

        lastT = T; lastbuf = buf;
    }

    // ---- drain: weighted sum for the final tile ----
    if (lastT >= 0) {
        const float* sEc = sE0 + lastbuf * 128 + h_ws * 64;
        const float* xprev = x + ((size_t)lastT * 128 + h_ws * 64) * DIM + d_ws;
        float wacc = 0.0f;
        #pragma unroll 16
        for (int t = 0; t < 64; t++)
            wacc = fmaf(sEc[t], __ldg(xprev + (size_t)t * DIM), wacc);
        if (h_ws == 0) sRed[d_ws] = wacc;
        __syncthreads();
        if (h_ws == 1)
            g_partial[(size_t)lastT * DIM + d_ws] = sRed[d_ws] + wacc;
    }
}

// ---------------- combine ----------------
__global__ void attn_finish(float* __restrict__ out) {
    const int b = blockIdx.x, d = threadIdx.x;
    float s = 0.0f, es = 0.0f;
    #pragma unroll
    for (int sp = 0; sp < 16; sp++) {
        s  += g_partial[(size_t)(b * 16 + sp) * DIM + d];
        es += g_esum[b * 16 + sp];
    }
    out[b * DIM + d] = s / (es + 1e-10f);
}

extern "C" void kernel_launch(void* const* d_in, const int* in_sizes, int n_in,
                              void* d_out, int out_size)
{
    const float* x    = (const float*)d_in[0];
    const float* w    = (const float*)d_in[1];
    const float* bias = (const float*)d_in[2];
    const float* cvec = (const float*)d_in[3];
    float* out = (float*)d_out;

    cudaFuncSetAttribute(attn_mma, cudaFuncAttributeMaxDynamicSharedMemorySize, SM_TOTAL);

    wprep<<<32, 256>>>(w);
    attn_mma<<<GRID, NTHR, SM_TOTAL>>>(x, bias, cvec);
    attn_finish<<<NBATCH, DIM>>>(out);
}